// round 15
// baseline (speedup 1.0000x reference)
#include <cuda_runtime.h>
#include <cuda_bf16.h>
#include <math.h>
#include <stdint.h>

#define RAD   5
#define Bz    4
#define Ktok  4096
#define Cdim  256
#define Hdim  128
#define NTOK  (Bz*Ktok)           // 16384
#define IBLK  8                   // rows per weighted block
#define NWBLK (NTOK/IBLK)         // 2048 weighted blocks
#define WROWS 8                   // rows per weights block
#define NWTBLK (NTOK/WROWS)       // 2048 weights blocks
#define NMMA  (NTOK/128)          // 128 MMA CTAs
#define CHPB  (NMMA/Bz)           // 32 stripes per batch

#define BUFB  32768               // bytes per tile buffer (Ah/Al/Bh/Bl 8KB each)

// ---------------- scratch ----------------
__device__ float  g_Tpart[NMMA*Cdim];    // per-CTA (128-token) col sums
__device__ float  g_e[NTOK];

// ---------------- helpers ----------------
__device__ __forceinline__ uint32_t smem_u32(const void* p) {
    return (uint32_t)__cvta_generic_to_shared(p);
}
#define LDSM4(r0, r1, r2, r3, addr) \
    asm volatile("ldmatrix.sync.aligned.m8n8.x4.shared.b16 {%0,%1,%2,%3}, [%4];" \
        : "=r"(r0), "=r"(r1), "=r"(r2), "=r"(r3) : "r"(addr))
#define MMA16816(d, a, b) \
    asm volatile("mma.sync.aligned.m16n8k16.row.col.f32.bf16.bf16.f32 " \
        "{%0,%1,%2,%3}, {%4,%5,%6,%7}, {%8,%9}, {%0,%1,%2,%3};" \
        : "+f"((d)[0]), "+f"((d)[1]), "+f"((d)[2]), "+f"((d)[3]) \
        : "r"((a)[0]), "r"((a)[1]), "r"((a)[2]), "r"((a)[3]), \
          "r"((b)[0]), "r"((b)[1]))

__device__ __forceinline__ uint64_t pk4(__nv_bfloat16 a, __nv_bfloat16 b,
                                        __nv_bfloat16 c, __nv_bfloat16 d) {
    uint16_t ua = *(uint16_t*)&a, ub = *(uint16_t*)&b;
    uint16_t uc = *(uint16_t*)&c, ud = *(uint16_t*)&d;
    return (uint64_t)ua | ((uint64_t)ub << 16) | ((uint64_t)uc << 32) | ((uint64_t)ud << 48);
}
__device__ __forceinline__ void split_bf16(float v, __nv_bfloat16& h, __nv_bfloat16& l) {
    h = __float2bfloat16(v);
    l = __float2bfloat16(v - __bfloat162float(h));
}

// ---------------- MLP via warp-mma bf16 split x3 + colsum -----------------
// Per CTA: 128 tokens x 128 hidden, K=256 in 8 chunks of 32.
// Double-buffered tiles (dynamic smem): store chunk k+1 overlaps mma chunk k.
__global__ void __launch_bounds__(256, 1)
k_mma(const float* __restrict__ x, const float* __restrict__ W1,
      const float* __restrict__ b1, const float* __restrict__ W2,
      const float* __restrict__ b2) {
    extern __shared__ __align__(16) char dsm[];   // 2 x 32KB tile buffers
    __shared__ float4 sredc[2][8][8];
    __shared__ float  sredE[128][2];
    __shared__ float  b1s[Hdim], w2s[Hdim];

    int tid = threadIdx.x;
    int wid = tid >> 5, lane = tid & 31;
    int wm = wid & 3, wn = wid >> 2;
    int m0 = blockIdx.x * 128;

    if (tid < Hdim) { b1s[tid] = b1[tid]; w2s[tid] = W2[tid]; }

    float acc[2][8][4];
    #pragma unroll
    for (int mf = 0; mf < 2; mf++)
        #pragma unroll
        for (int nf = 0; nf < 8; nf++)
            #pragma unroll
            for (int c = 0; c < 4; c++) acc[mf][nf][c] = 0.f;

    int f8 = tid & 7;
    int bn = tid & 127, bkh = (tid >> 7) * 16;
    float4 xv[4];
    float  bv[16];

    // ---- store one chunk's tiles + colsum partial into buffer sb ----
    auto store_chunk = [&](int sb) {
        char* Ah = dsm + sb * BUFB;
        char* Al = Ah + 8192;
        char* Bh = Ah + 16384;
        char* Bl = Ah + 24576;
        float4 ps = make_float4(0.f, 0.f, 0.f, 0.f);
        #pragma unroll
        for (int q = 0; q < 4; q++) {
            int row = q * 32 + (tid >> 3);
            float4 v = xv[q];
            ps.x += v.x; ps.y += v.y; ps.z += v.z; ps.w += v.w;
            __nv_bfloat16 h0,l0,h1,l1,h2,l2,h3,l3;
            split_bf16(v.x, h0, l0); split_bf16(v.y, h1, l1);
            split_bf16(v.z, h2, l2); split_bf16(v.w, h3, l3);
            uint32_t off = (uint32_t)(row * 64 + f8 * 8);
            uint32_t sw = off ^ (((uint32_t)(row & 7)) << 4);
            *(uint64_t*)(Ah + sw) = pk4(h0, h1, h2, h3);
            *(uint64_t*)(Al + sw) = pk4(l0, l1, l2, l3);
        }
        #pragma unroll
        for (int g = 0; g < 4; g++) {
            __nv_bfloat16 h0,l0,h1,l1,h2,l2,h3,l3;
            split_bf16(bv[g*4+0], h0, l0); split_bf16(bv[g*4+1], h1, l1);
            split_bf16(bv[g*4+2], h2, l2); split_bf16(bv[g*4+3], h3, l3);
            uint32_t off = (uint32_t)(bn * 64 + (bkh + g*4) * 2);
            uint32_t sw = off ^ (((uint32_t)(bn & 7)) << 4);
            *(uint64_t*)(Bh + sw) = pk4(h0, h1, h2, h3);
            *(uint64_t*)(Bl + sw) = pk4(l0, l1, l2, l3);
        }
        ps.x += __shfl_xor_sync(0xffffffffu, ps.x, 8);
        ps.y += __shfl_xor_sync(0xffffffffu, ps.y, 8);
        ps.z += __shfl_xor_sync(0xffffffffu, ps.z, 8);
        ps.w += __shfl_xor_sync(0xffffffffu, ps.w, 8);
        ps.x += __shfl_xor_sync(0xffffffffu, ps.x, 16);
        ps.y += __shfl_xor_sync(0xffffffffu, ps.y, 16);
        ps.z += __shfl_xor_sync(0xffffffffu, ps.z, 16);
        ps.w += __shfl_xor_sync(0xffffffffu, ps.w, 16);
        if (lane < 8) sredc[sb][wid][lane] = ps;
    };
    auto prefetch_chunk = [&](int kc) {
        #pragma unroll
        for (int q = 0; q < 4; q++) {
            int row = q * 32 + (tid >> 3);
            xv[q] = *(const float4*)&x[(size_t)(m0 + row)*Cdim + kc + f8*4];
        }
        #pragma unroll
        for (int j = 0; j < 16; j++)
            bv[j] = W1[(size_t)(kc + bkh + j)*Hdim + bn];
    };
    auto finalize_colsum = [&](int sb, int kc) {
        if (tid < 32) {
            float s = 0.f;
            #pragma unroll
            for (int w = 0; w < 8; w++) {
                const float* f = (const float*)&sredc[sb][w][tid >> 2];
                s += f[tid & 3];
            }
            g_Tpart[(size_t)blockIdx.x * Cdim + kc + tid] = s;
        }
    };

    // ---- prologue: chunk 0 ----
    prefetch_chunk(0);
    store_chunk(0);
    prefetch_chunk(32);
    __syncthreads();
    finalize_colsum(0, 0);

    for (int ck = 0; ck < 8; ck++) {
        int buf = ck & 1;
        // store chunk ck+1 into other buffer (overlaps with mma below)
        if (ck < 7) store_chunk(buf ^ 1);
        if (ck < 6) prefetch_chunk((ck + 2) * 32);

        // mma chunk ck from tiles[buf]
        {
            char* base = dsm + buf * BUFB;
            uint32_t ah_b = smem_u32(base);
            uint32_t al_b = smem_u32(base + 8192);
            uint32_t bh_b = smem_u32(base + 16384);
            uint32_t bl_b = smem_u32(base + 24576);
            #pragma unroll
            for (int ks = 0; ks < 2; ks++) {
                uint32_t ahf[2][4], alf[2][4], bhf[8][2], blf[8][2];
                #pragma unroll
                for (int mf = 0; mf < 2; mf++) {
                    int subm = lane >> 3, r = lane & 7;
                    int m = wm*32 + mf*16 + ((subm & 1) << 3) + r;
                    int kb = ks*16 + ((subm & 2) << 2);
                    uint32_t off = (uint32_t)(m * 64 + kb * 2)
                                 ^ (((uint32_t)(m & 7)) << 4);
                    LDSM4(ahf[mf][0], ahf[mf][1], ahf[mf][2], ahf[mf][3], ah_b + off);
                    LDSM4(alf[mf][0], alf[mf][1], alf[mf][2], alf[mf][3], al_b + off);
                }
                #pragma unroll
                for (int nf2 = 0; nf2 < 4; nf2++) {
                    int grp = lane >> 3, r = lane & 7;
                    int n = wn*64 + nf2*16 + ((grp & 2) << 2) + r;
                    int kb = ks*16 + ((grp & 1) << 3);
                    uint32_t off = (uint32_t)(n * 64 + kb * 2)
                                 ^ (((uint32_t)(n & 7)) << 4);
                    LDSM4(bhf[nf2*2][0], bhf[nf2*2][1],
                          bhf[nf2*2+1][0], bhf[nf2*2+1][1], bh_b + off);
                    LDSM4(blf[nf2*2][0], blf[nf2*2][1],
                          blf[nf2*2+1][0], blf[nf2*2+1][1], bl_b + off);
                }
                #pragma unroll
                for (int mf = 0; mf < 2; mf++)
                    #pragma unroll
                    for (int nf = 0; nf < 8; nf++)
                        MMA16816(acc[mf][nf], ahf[mf], bhf[nf]);
                #pragma unroll
                for (int mf = 0; mf < 2; mf++)
                    #pragma unroll
                    for (int nf = 0; nf < 8; nf++)
                        MMA16816(acc[mf][nf], alf[mf], bhf[nf]);
                #pragma unroll
                for (int mf = 0; mf < 2; mf++)
                    #pragma unroll
                    for (int nf = 0; nf < 8; nf++)
                        MMA16816(acc[mf][nf], ahf[mf], blf[nf]);
            }
        }
        __syncthreads();
        if (ck < 7) finalize_colsum(buf ^ 1, (ck + 1) * 32);
    }

    // ---- epilogue (unchanged) ----
    float p[2][2] = {{0.f, 0.f}, {0.f, 0.f}};
    #pragma unroll
    for (int mf = 0; mf < 2; mf++)
        #pragma unroll
        for (int nf = 0; nf < 8; nf++) {
            int n0 = wn*64 + nf*8 + ((lane & 3) << 1);
            float b1a = b1s[n0], w2a = w2s[n0];
            float b1b = b1s[n0 + 1], w2b = w2s[n0 + 1];
            p[mf][0] += tanhf(acc[mf][nf][0] + b1a) * w2a
                      + tanhf(acc[mf][nf][1] + b1b) * w2b;
            p[mf][1] += tanhf(acc[mf][nf][2] + b1a) * w2a
                      + tanhf(acc[mf][nf][3] + b1b) * w2b;
        }
    #pragma unroll
    for (int mf = 0; mf < 2; mf++)
        #pragma unroll
        for (int h = 0; h < 2; h++) {
            p[mf][h] += __shfl_xor_sync(0xffffffffu, p[mf][h], 1);
            p[mf][h] += __shfl_xor_sync(0xffffffffu, p[mf][h], 2);
        }
    __syncthreads();
    if ((lane & 3) == 0) {
        #pragma unroll
        for (int mf = 0; mf < 2; mf++)
            #pragma unroll
            for (int h = 0; h < 2; h++)
                sredE[wm*32 + mf*16 + h*8 + (lane >> 2)][wn] = p[mf][h];
    }
    __syncthreads();
    if (tid < 128)
        g_e[m0 + tid] = expf(sredE[tid][0] + sredE[tid][1] + b2[0]);
}

// ---------------- fused output: 1:1 interleave (R12, proven) --------------
__global__ void __launch_bounds__(256) k_fused(const float* __restrict__ x,
                                               float* __restrict__ wout,
                                               float* __restrict__ outw) {
    __shared__ float xs[(IBLK + 2*RAD) * Cdim];   // 18KB
    __shared__ float em1[32];
    __shared__ float invs[IBLK];

    int bid = blockIdx.x;              // 0..4095
    int tid = threadIdx.x;
    int g2 = bid & 1;
    int q  = bid >> 1;                 // 0..2047

    if (g2 != 0) {
        int r0 = q * WROWS;
        int b = r0 >> 12, i0 = r0 & (Ktok - 1);
        int jlo0 = max(i0 - RAD, 0);
        int jhi0 = min(i0 + WROWS - 1 + RAD, Ktok - 1);
        int n = jhi0 - jlo0 + 1;                  // <= 18
        float* sev  = xs;
        float* sinv = xs + 32;
        if (tid < n) sev[tid] = g_e[((size_t)b << 12) + jlo0 + tid];
        __syncthreads();
        if (tid < WROWS) {
            int i = i0 + tid;
            int jl = max(i - RAD, 0), jh = min(i + RAD, Ktok - 1);
            float s = (float)(Ktok - (jh - jl + 1));
            for (int j = jl; j <= jh; j++) s += sev[j - jlo0];
            sinv[tid] = 1.0f / s;
        }
        __syncthreads();

        #pragma unroll
        for (int ii = 0; ii < WROWS; ii++) {
            int i = i0 + ii;
            float inv = sinv[ii];
            int jlo = max(i - RAD, 0), jhi = min(i + RAD, Ktok - 1);
            float* row = wout + (size_t)(r0 + ii) * Ktok;
            float4 v4 = make_float4(inv, inv, inv, inv);
            #pragma unroll
            for (int q2 = 0; q2 < 4; q2++) {
                int jj = (q2 << 10) + (tid << 2);
                float4 t = v4;
                if (jj + 3 >= jlo && jj <= jhi) {
                    if (jj + 0 >= jlo && jj + 0 <= jhi) t.x = sev[jj + 0 - jlo0] * inv;
                    if (jj + 1 >= jlo && jj + 1 <= jhi) t.y = sev[jj + 1 - jlo0] * inv;
                    if (jj + 2 >= jlo && jj + 2 <= jhi) t.z = sev[jj + 2 - jlo0] * inv;
                    if (jj + 3 >= jlo && jj + 3 <= jhi) t.w = sev[jj + 3 - jlo0] * inv;
                }
                __stcs((float4*)&row[jj], t);
            }
        }
    } else {
        int b = q >> 9;                           // 512 blocks per batch
        int i0 = (q & 511) << 3;
        int jlo = max(i0 - RAD, 0);
        int jhi = min(i0 + IBLK - 1 + RAD, Ktok - 1);
        int n = jhi - jlo + 1;                    // <= 18

        const float* xb = x + (((size_t)b << 12) + jlo) * Cdim;
        for (int idx = tid; idx < n * Cdim; idx += 256)
            xs[idx] = xb[idx];
        if (tid < n) em1[tid] = g_e[((size_t)b << 12) + jlo + tid];
        __syncthreads();

        if (tid < IBLK) {
            int i = i0 + tid;
            int jl = max(i - RAD, 0), jh = min(i + RAD, Ktok - 1);
            float s = (float)(Ktok - (jh - jl + 1));
            for (int j = jl; j <= jh; j++) s += em1[j - jlo];
            invs[tid] = 1.0f / s;
        }
        float Tc = 0.f;
        #pragma unroll
        for (int ch = 0; ch < CHPB; ch++)
            Tc += g_Tpart[(size_t)(b*CHPB + ch)*Cdim + tid];
        __syncthreads();
        if (tid < n) em1[tid] -= 1.0f;
        __syncthreads();

        int c = tid;
        float* op = outw + (((size_t)b << 12) + i0) * Cdim + c;
        #pragma unroll
        for (int ii = 0; ii < IBLK; ii++) {
            int i = i0 + ii;
            int lo = max(i - RAD, 0) - jlo;
            int hi = min(i + RAD, Ktok - 1) - jlo;
            float acc = Tc;
            for (int r = lo; r <= hi; r++) acc += em1[r] * xs[r * Cdim + c];
            __stcs(&op[(size_t)ii * Cdim], acc * invs[ii]);
        }
    }
}

// ---------------- launch ----------------
extern "C" void kernel_launch(void* const* d_in, const int* in_sizes, int n_in,
                              void* d_out, int out_size) {
    (void)in_sizes; (void)n_in; (void)out_size;
    const float* x  = (const float*)d_in[0];
    const float* W1 = (const float*)d_in[1];
    const float* b1 = (const float*)d_in[2];
    const float* W2 = (const float*)d_in[3];
    const float* b2 = (const float*)d_in[4];

    float* out_weighted = (float*)d_out;
    float* out_weights  = (float*)d_out + (size_t)NTOK * Cdim;

    const int dyn = 2 * BUFB;   // 64KB double-buffered tiles
    static int set_done = 0;
    if (!set_done) {
        cudaFuncSetAttribute(k_mma, cudaFuncAttributeMaxDynamicSharedMemorySize, dyn);
        set_done = 1;
    }

    k_mma  <<<NMMA,           256, dyn>>>(x, W1, b1, W2, b2);
    k_fused<<<NWBLK + NWTBLK, 256>>>(x, out_weights, out_weighted);
}

// round 16
// speedup vs baseline: 1.5838x; 1.5838x over previous
#include <cuda_runtime.h>
#include <cuda_bf16.h>
#include <math.h>
#include <stdint.h>

#define RAD   5
#define Bz    4
#define Ktok  4096
#define Cdim  256
#define Hdim  128
#define NTOK  (Bz*Ktok)           // 16384
#define IBLK  8                   // rows per weighted block
#define NWBLK (NTOK/IBLK)         // 2048 weighted blocks
#define WROWS 8                   // rows per weights block
#define NWTBLK (NTOK/WROWS)       // 2048 weights blocks
#define NMMA  (NTOK/128)          // 128 MMA CTAs
#define CHPB  (NMMA/Bz)           // 32 chunks per batch

// ---------------- scratch ----------------
__device__ float  g_Tpart[NMMA*Cdim];    // per-CTA (128-token) col sums
__device__ float  g_e[NTOK];

// ---------------- helpers ----------------
__device__ __forceinline__ uint32_t smem_u32(const void* p) {
    return (uint32_t)__cvta_generic_to_shared(p);
}
#define LDSM4(r0, r1, r2, r3, addr) \
    asm volatile("ldmatrix.sync.aligned.m8n8.x4.shared.b16 {%0,%1,%2,%3}, [%4];" \
        : "=r"(r0), "=r"(r1), "=r"(r2), "=r"(r3) : "r"(addr))
#define MMA16816(d, a, b) \
    asm volatile("mma.sync.aligned.m16n8k16.row.col.f32.bf16.bf16.f32 " \
        "{%0,%1,%2,%3}, {%4,%5,%6,%7}, {%8,%9}, {%0,%1,%2,%3};" \
        : "+f"((d)[0]), "+f"((d)[1]), "+f"((d)[2]), "+f"((d)[3]) \
        : "r"((a)[0]), "r"((a)[1]), "r"((a)[2]), "r"((a)[3]), \
          "r"((b)[0]), "r"((b)[1]))

__device__ __forceinline__ uint64_t pk4(__nv_bfloat16 a, __nv_bfloat16 b,
                                        __nv_bfloat16 c, __nv_bfloat16 d) {
    uint16_t ua = *(uint16_t*)&a, ub = *(uint16_t*)&b;
    uint16_t uc = *(uint16_t*)&c, ud = *(uint16_t*)&d;
    return (uint64_t)ua | ((uint64_t)ub << 16) | ((uint64_t)uc << 32) | ((uint64_t)ud << 48);
}
__device__ __forceinline__ void split_bf16(float v, __nv_bfloat16& h, __nv_bfloat16& l) {
    h = __float2bfloat16(v);
    l = __float2bfloat16(v - __bfloat162float(h));
}

// ---------------- MLP via warp-mma bf16 split x3 + colsum (R10, proven) ---
__global__ void __launch_bounds__(256, 1)
k_mma(const float* __restrict__ x, const float* __restrict__ W1,
      const float* __restrict__ b1, const float* __restrict__ W2,
      const float* __restrict__ b2) {
    __shared__ __align__(16) char Ah[128*64];
    __shared__ __align__(16) char Al[128*64];
    __shared__ __align__(16) char Bh[128*64];
    __shared__ __align__(16) char Bl[128*64];
    __shared__ float4 sredc[8][8];
    __shared__ float  sredE[128][2];
    __shared__ float  b1s[Hdim], w2s[Hdim];

    int tid = threadIdx.x;
    int wid = tid >> 5, lane = tid & 31;
    int wm = wid & 3, wn = wid >> 2;
    int m0 = blockIdx.x * 128;

    if (tid < Hdim) { b1s[tid] = b1[tid]; w2s[tid] = W2[tid]; }

    uint32_t ah_b = smem_u32(Ah), al_b = smem_u32(Al);
    uint32_t bh_b = smem_u32(Bh), bl_b = smem_u32(Bl);

    float acc[2][8][4];
    #pragma unroll
    for (int mf = 0; mf < 2; mf++)
        #pragma unroll
        for (int nf = 0; nf < 8; nf++)
            #pragma unroll
            for (int c = 0; c < 4; c++) acc[mf][nf][c] = 0.f;

    int f8 = tid & 7;
    int bn = tid & 127, bkh = (tid >> 7) * 16;
    float4 xv[4];
    float  bv[16];
    {
        #pragma unroll
        for (int q = 0; q < 4; q++) {
            int row = q * 32 + (tid >> 3);
            xv[q] = *(const float4*)&x[(size_t)(m0 + row)*Cdim + f8*4];
        }
        #pragma unroll
        for (int j = 0; j < 16; j++)
            bv[j] = W1[(size_t)(bkh + j)*Hdim + bn];
    }

    for (int ck = 0; ck < 8; ck++) {
        int kc = ck * 32;
        __syncthreads();

        float4 ps = make_float4(0.f, 0.f, 0.f, 0.f);
        #pragma unroll
        for (int q = 0; q < 4; q++) {
            int row = q * 32 + (tid >> 3);
            float4 v = xv[q];
            ps.x += v.x; ps.y += v.y; ps.z += v.z; ps.w += v.w;
            __nv_bfloat16 h0,l0,h1,l1,h2,l2,h3,l3;
            split_bf16(v.x, h0, l0); split_bf16(v.y, h1, l1);
            split_bf16(v.z, h2, l2); split_bf16(v.w, h3, l3);
            uint32_t off = (uint32_t)(row * 64 + f8 * 8);
            uint32_t sw = off ^ (((uint32_t)(row & 7)) << 4);
            *(uint64_t*)(Ah + sw) = pk4(h0, h1, h2, h3);
            *(uint64_t*)(Al + sw) = pk4(l0, l1, l2, l3);
        }
        #pragma unroll
        for (int g = 0; g < 4; g++) {
            __nv_bfloat16 h0,l0,h1,l1,h2,l2,h3,l3;
            split_bf16(bv[g*4+0], h0, l0); split_bf16(bv[g*4+1], h1, l1);
            split_bf16(bv[g*4+2], h2, l2); split_bf16(bv[g*4+3], h3, l3);
            uint32_t off = (uint32_t)(bn * 64 + (bkh + g*4) * 2);
            uint32_t sw = off ^ (((uint32_t)(bn & 7)) << 4);
            *(uint64_t*)(Bh + sw) = pk4(h0, h1, h2, h3);
            *(uint64_t*)(Bl + sw) = pk4(l0, l1, l2, l3);
        }
        ps.x += __shfl_xor_sync(0xffffffffu, ps.x, 8);
        ps.y += __shfl_xor_sync(0xffffffffu, ps.y, 8);
        ps.z += __shfl_xor_sync(0xffffffffu, ps.z, 8);
        ps.w += __shfl_xor_sync(0xffffffffu, ps.w, 8);
        ps.x += __shfl_xor_sync(0xffffffffu, ps.x, 16);
        ps.y += __shfl_xor_sync(0xffffffffu, ps.y, 16);
        ps.z += __shfl_xor_sync(0xffffffffu, ps.z, 16);
        ps.w += __shfl_xor_sync(0xffffffffu, ps.w, 16);
        if (lane < 8) sredc[wid][lane] = ps;
        __syncthreads();

        if (tid < 32) {
            float s = 0.f;
            #pragma unroll
            for (int w = 0; w < 8; w++) {
                const float* f = (const float*)&sredc[w][tid >> 2];
                s += f[tid & 3];
            }
            g_Tpart[(size_t)blockIdx.x * Cdim + kc + tid] = s;
        }

        if (ck < 7) {
            int kn = kc + 32;
            #pragma unroll
            for (int q = 0; q < 4; q++) {
                int row = q * 32 + (tid >> 3);
                xv[q] = *(const float4*)&x[(size_t)(m0 + row)*Cdim + kn + f8*4];
            }
            #pragma unroll
            for (int j = 0; j < 16; j++)
                bv[j] = W1[(size_t)(kn + bkh + j)*Hdim + bn];
        }

        #pragma unroll
        for (int ks = 0; ks < 2; ks++) {
            uint32_t ahf[2][4], alf[2][4], bhf[8][2], blf[8][2];
            #pragma unroll
            for (int mf = 0; mf < 2; mf++) {
                int subm = lane >> 3, r = lane & 7;
                int m = wm*32 + mf*16 + ((subm & 1) << 3) + r;
                int kb = ks*16 + ((subm & 2) << 2);
                uint32_t off = (uint32_t)(m * 64 + kb * 2)
                             ^ (((uint32_t)(m & 7)) << 4);
                LDSM4(ahf[mf][0], ahf[mf][1], ahf[mf][2], ahf[mf][3], ah_b + off);
                LDSM4(alf[mf][0], alf[mf][1], alf[mf][2], alf[mf][3], al_b + off);
            }
            #pragma unroll
            for (int nf2 = 0; nf2 < 4; nf2++) {
                int grp = lane >> 3, r = lane & 7;
                int n = wn*64 + nf2*16 + ((grp & 2) << 2) + r;
                int kb = ks*16 + ((grp & 1) << 3);
                uint32_t off = (uint32_t)(n * 64 + kb * 2)
                             ^ (((uint32_t)(n & 7)) << 4);
                LDSM4(bhf[nf2*2][0], bhf[nf2*2][1],
                      bhf[nf2*2+1][0], bhf[nf2*2+1][1], bh_b + off);
                LDSM4(blf[nf2*2][0], blf[nf2*2][1],
                      blf[nf2*2+1][0], blf[nf2*2+1][1], bl_b + off);
            }
            #pragma unroll
            for (int mf = 0; mf < 2; mf++)
                #pragma unroll
                for (int nf = 0; nf < 8; nf++)
                    MMA16816(acc[mf][nf], ahf[mf], bhf[nf]);
            #pragma unroll
            for (int mf = 0; mf < 2; mf++)
                #pragma unroll
                for (int nf = 0; nf < 8; nf++)
                    MMA16816(acc[mf][nf], alf[mf], bhf[nf]);
            #pragma unroll
            for (int mf = 0; mf < 2; mf++)
                #pragma unroll
                for (int nf = 0; nf < 8; nf++)
                    MMA16816(acc[mf][nf], ahf[mf], blf[nf]);
        }
    }

    float p[2][2] = {{0.f, 0.f}, {0.f, 0.f}};
    #pragma unroll
    for (int mf = 0; mf < 2; mf++)
        #pragma unroll
        for (int nf = 0; nf < 8; nf++) {
            int n0 = wn*64 + nf*8 + ((lane & 3) << 1);
            float b1a = b1s[n0], w2a = w2s[n0];
            float b1b = b1s[n0 + 1], w2b = w2s[n0 + 1];
            p[mf][0] += tanhf(acc[mf][nf][0] + b1a) * w2a
                      + tanhf(acc[mf][nf][1] + b1b) * w2b;
            p[mf][1] += tanhf(acc[mf][nf][2] + b1a) * w2a
                      + tanhf(acc[mf][nf][3] + b1b) * w2b;
        }
    #pragma unroll
    for (int mf = 0; mf < 2; mf++)
        #pragma unroll
        for (int h = 0; h < 2; h++) {
            p[mf][h] += __shfl_xor_sync(0xffffffffu, p[mf][h], 1);
            p[mf][h] += __shfl_xor_sync(0xffffffffu, p[mf][h], 2);
        }
    __syncthreads();
    if ((lane & 3) == 0) {
        #pragma unroll
        for (int mf = 0; mf < 2; mf++)
            #pragma unroll
            for (int h = 0; h < 2; h++)
                sredE[wm*32 + mf*16 + h*8 + (lane >> 2)][wn] = p[mf][h];
    }
    __syncthreads();
    if (tid < 128)
        g_e[m0 + tid] = expf(sredE[tid][0] + sredE[tid][1] + b2[0]);
}

// ---------------- fused output: 1:1 interleave, IBLK=8 (R12, proven) ------
__global__ void __launch_bounds__(256) k_fused(const float* __restrict__ x,
                                               float* __restrict__ wout,
                                               float* __restrict__ outw) {
    __shared__ float xs[(IBLK + 2*RAD) * Cdim];   // 18KB
    __shared__ float em1[32];
    __shared__ float invs[IBLK];

    int bid = blockIdx.x;              // 0..4095
    int tid = threadIdx.x;
    int g2 = bid & 1;
    int q  = bid >> 1;                 // 0..2047

    if (g2 != 0) {
        // ---- weights fill: 8 rows per block, 128KB streamed store ----
        int r0 = q * WROWS;
        int b = r0 >> 12, i0 = r0 & (Ktok - 1);
        int jlo0 = max(i0 - RAD, 0);
        int jhi0 = min(i0 + WROWS - 1 + RAD, Ktok - 1);
        int n = jhi0 - jlo0 + 1;                  // <= 18
        float* sev  = xs;
        float* sinv = xs + 32;
        if (tid < n) sev[tid] = g_e[((size_t)b << 12) + jlo0 + tid];
        __syncthreads();
        if (tid < WROWS) {
            int i = i0 + tid;
            int jl = max(i - RAD, 0), jh = min(i + RAD, Ktok - 1);
            float s = (float)(Ktok - (jh - jl + 1));
            for (int j = jl; j <= jh; j++) s += sev[j - jlo0];
            sinv[tid] = 1.0f / s;
        }
        __syncthreads();

        #pragma unroll
        for (int ii = 0; ii < WROWS; ii++) {
            int i = i0 + ii;
            float inv = sinv[ii];
            int jlo = max(i - RAD, 0), jhi = min(i + RAD, Ktok - 1);
            float* row = wout + (size_t)(r0 + ii) * Ktok;
            float4 v4 = make_float4(inv, inv, inv, inv);
            #pragma unroll
            for (int q2 = 0; q2 < 4; q2++) {
                int jj = (q2 << 10) + (tid << 2);
                float4 t = v4;
                if (jj + 3 >= jlo && jj <= jhi) {
                    if (jj + 0 >= jlo && jj + 0 <= jhi) t.x = sev[jj + 0 - jlo0] * inv;
                    if (jj + 1 >= jlo && jj + 1 <= jhi) t.y = sev[jj + 1 - jlo0] * inv;
                    if (jj + 2 >= jlo && jj + 2 <= jhi) t.z = sev[jj + 2 - jlo0] * inv;
                    if (jj + 3 >= jlo && jj + 3 <= jhi) t.w = sev[jj + 3 - jlo0] * inv;
                }
                __stcs((float4*)&row[jj], t);
            }
        }
    } else {
        // ---- weighted rows: 8 per block ----
        int b = q >> 9;                           // 512 blocks per batch
        int i0 = (q & 511) << 3;
        int jlo = max(i0 - RAD, 0);
        int jhi = min(i0 + IBLK - 1 + RAD, Ktok - 1);
        int n = jhi - jlo + 1;                    // <= 18

        const float* xb = x + (((size_t)b << 12) + jlo) * Cdim;
        for (int idx = tid; idx < n * Cdim; idx += 256)
            xs[idx] = xb[idx];
        if (tid < n) em1[tid] = g_e[((size_t)b << 12) + jlo + tid];
        __syncthreads();

        // local 1/denom (ascending order)
        if (tid < IBLK) {
            int i = i0 + tid;
            int jl = max(i - RAD, 0), jh = min(i + RAD, Ktok - 1);
            float s = (float)(Ktok - (jh - jl + 1));
            for (int j = jl; j <= jh; j++) s += em1[j - jlo];
            invs[tid] = 1.0f / s;
        }
        // T self-reduce in fp32 (fixed order over 32 chunks, L2-resident)
        float Tc = 0.f;
        #pragma unroll
        for (int ch = 0; ch < CHPB; ch++)
            Tc += g_Tpart[(size_t)(b*CHPB + ch)*Cdim + tid];
        __syncthreads();
        if (tid < n) em1[tid] -= 1.0f;
        __syncthreads();

        int c = tid;
        float* op = outw + (((size_t)b << 12) + i0) * Cdim + c;
        #pragma unroll
        for (int ii = 0; ii < IBLK; ii++) {
            int i = i0 + ii;
            int lo = max(i - RAD, 0) - jlo;
            int hi = min(i + RAD, Ktok - 1) - jlo;
            float acc = Tc;
            for (int r = lo; r <= hi; r++) acc += em1[r] * xs[r * Cdim + c];
            __stcs(&op[(size_t)ii * Cdim], acc * invs[ii]);
        }
    }
}

// ---------------- launch ----------------
extern "C" void kernel_launch(void* const* d_in, const int* in_sizes, int n_in,
                              void* d_out, int out_size) {
    (void)in_sizes; (void)n_in; (void)out_size;
    const float* x  = (const float*)d_in[0];
    const float* W1 = (const float*)d_in[1];
    const float* b1 = (const float*)d_in[2];
    const float* W2 = (const float*)d_in[3];
    const float* b2 = (const float*)d_in[4];

    float* out_weighted = (float*)d_out;
    float* out_weights  = (float*)d_out + (size_t)NTOK * Cdim;

    k_mma  <<<NMMA,           256>>>(x, W1, b1, W2, b2);
    k_fused<<<NWBLK + NWTBLK, 256>>>(x, out_weights, out_weighted);
}